// round 11
// baseline (speedup 1.0000x reference)
#include <cuda_runtime.h>
#include <math.h>
#include <stdint.h>

// Fixed problem shapes
#define BB   4
#define SS   2048
#define GG   8
#define DD   128
#define NN   64
#define BG   (BB*GG)          // 32
#define NTOK (BB*SS*GG)       // 65536
#define SUB  32
#define NSUB (SS/SUB)         // 64

// Scratch (device globals; no allocation allowed)
__device__ float2 g_abr[BG*SS*NN];     // (a_r, bxr*dt)  32 MB
__device__ float2 g_abi[BG*SS*NN];     // (a_i, bxi*dt)  32 MB
__device__ float4 g_hc[BG*SS*NN];      // (hl_r, hl_i, c_r, c_i)  64 MB
__device__ float2 g_hin[BG*NSUB*NN];   // subchunk input states    1 MB

// ---------------- helpers ----------------
__device__ __forceinline__ uint32_t cvt_tf32(float f) {
    uint32_t u; asm("cvt.rna.tf32.f32 %0, %1;" : "=r"(u) : "f"(f)); return u;
}
__device__ __forceinline__ float tf32f(float f) {
    return __uint_as_float(cvt_tf32(f));
}
__device__ __forceinline__ void mma8(float* c, uint32_t a0, uint32_t a1,
                                     uint32_t a2, uint32_t a3,
                                     uint32_t b0, uint32_t b1) {
    asm("mma.sync.aligned.m16n8k8.row.col.f32.tf32.tf32.f32 "
        "{%0,%1,%2,%3}, {%4,%5,%6,%7}, {%8,%9}, {%0,%1,%2,%3};"
        : "+f"(c[0]), "+f"(c[1]), "+f"(c[2]), "+f"(c[3])
        : "r"(a0), "r"(a1), "r"(a2), "r"(a3), "r"(b0), "r"(b1));
}
__device__ __forceinline__ float clampdt(float v) {
    return fminf(fmaxf(v, 1e-4f), 2.0f);
}
// packed column position: pairs (k, k+4) adjacent for LDS.64 fragment loads
__device__ __forceinline__ int unpos(int c) {
    int slot = c & 7;
    return (c & ~7) + (slot >> 1) + ((slot & 1) << 2);
}
__device__ __forceinline__ int posf(int k) {
    return (k & ~7) + ((k & 3) << 1) + ((k & 4) >> 2);
}
// exp(z) on [-2.75, 0.05]: Taylor deg-10 about -1.375 (abs err < 1e-6)
__device__ __forceinline__ float pexp(float z) {
    const float t = z + 1.375f;
    float r = 6.96758145405495e-08f;
    r = fmaf(r, t, 6.96758145405495e-07f);
    r = fmaf(r, t, 6.27082330864946e-06f);
    r = fmaf(r, t, 5.01665864691957e-05f);
    r = fmaf(r, t, 3.51166105284370e-04f);
    r = fmaf(r, t, 2.10699663170622e-03f);
    r = fmaf(r, t, 1.05349831585311e-02f);
    r = fmaf(r, t, 4.21399326341243e-02f);
    r = fmaf(r, t, 1.26419797902373e-01f);
    r = fmaf(r, t, 2.52839595804746e-01f);
    r = fmaf(r, t, 2.52839595804746e-01f);
    return r;
}
// sin Taylor, |w| <= 2 (abs err < 2e-6)
__device__ __forceinline__ float psin(float w) {
    float w2 = w * w;
    float sr = -2.50521083854417e-08f;
    sr = fmaf(sr, w2, 2.75573192239859e-06f);
    sr = fmaf(sr, w2, -1.98412698412698e-04f);
    sr = fmaf(sr, w2, 8.33333333333333e-03f);
    sr = fmaf(sr, w2, -1.66666666666667e-01f);
    return fmaf(sr * w2, w, w);
}
// cos Taylor, |w| <= 2 (abs err < 2e-6)
__device__ __forceinline__ float pcos(float w) {
    float w2 = w * w;
    float cr = 2.08767569878681e-09f;
    cr = fmaf(cr, w2, -2.75573192239859e-07f);
    cr = fmaf(cr, w2, 2.48015873015873e-05f);
    cr = fmaf(cr, w2, -1.38888888888889e-03f);
    cr = fmaf(cr, w2, 4.16666666666667e-02f);
    cr = fmaf(cr, w2, -5.0e-01f);
    return fmaf(cr, w2, 1.0f);
}

// ---------------------------------------------------------------------------
// Kernel 1: tf32 MMA projection, cr/ci warp-split. CTA = 128 tokens, 512 thr,
// 16 warps = 8 token-groups x {real pass, imag pass}. Real pass: 9 nt tiles
// (Bwr / -Bwi, plus dt columns); imag pass: 8 nt (Bwi / Bwr). dt exchanged
// via smem; each half writes its own float2 array (g_abr / g_abi).
// ---------------------------------------------------------------------------
__global__ __launch_bounds__(512, 2) void k1_mma(
    const float* __restrict__ xr_g, const float* __restrict__ xi_g,
    const float* __restrict__ logA, const float* __restrict__ Aph_g,
    const float* __restrict__ Bwr,  const float* __restrict__ Bwi,
    const float* __restrict__ dtw_g, const float* __restrict__ dtb_g)
{
    extern __shared__ float sm[];
    float*  BRp  = sm;                   // [72][136]
    float*  BIp  = BRp + 72*136;         // [72][136]
    float*  nlA  = BIp + 72*136;         // [512]
    float*  aph  = nlA + 512;            // [512]
    float2* dts  = (float2*)(aph + 512); // [128] (dm, dp) per token

    const int tid = threadIdx.x;
    for (int idx = tid; idx < 72*136; idx += 512) {
        int r = idx / 136, c = idx - r*136;
        float vr = 0.f, vi = 0.f;
        if (c < 128 && r < 66) {
            int k = unpos(c);
            if (r < 64)      { vr = Bwr[r*128 + k];   vi = Bwi[r*128 + k]; }
            else if (r == 64){ vr = dtw_g[k];         vi = dtw_g[128 + k]; }
            else             { vr = dtw_g[256 + k];   vi = dtw_g[384 + k]; }
        }
        BRp[idx] = tf32f(vr);
        BIp[idx] = tf32f(vi);
    }
    for (int i = tid; i < 512; i += 512) { }   // (no-op; keep loop shapes simple)
    if (tid < 512) {
        nlA[tid] = -log1pf(expf(logA[tid]));   // -softplus
        aph[tid] = Aph_g[tid];
    }
    __syncthreads();

    const int w = tid >> 5, l = tid & 31;
    const int q = l >> 2, j = l & 3;
    const int pass = w >> 3;          // 0 = real (cr), 1 = imag (ci)
    const int tokg = w & 7;
    const int tau0 = blockIdx.x*128 + tokg*16;
    const int b = tau0 >> 14;
    const int s0 = (tau0 >> 3) & 2047;

    const size_t rowA = (size_t)(tau0 + q)*128;
    const size_t rowB = (size_t)(tau0 + q + 8)*128;

    float acc[9][4];
    #pragma unroll
    for (int t = 0; t < 9; ++t) { acc[t][0]=0.f; acc[t][1]=0.f; acc[t][2]=0.f; acc[t][3]=0.f; }

    if (pass == 0) {
        // ---- real pass: Bx_r (+dt) ----
        #pragma unroll 2
        for (int ks = 0; ks < 16; ++ks) {
            const int kk = ks*8 + j;
            uint32_t a0 = cvt_tf32(xr_g[rowA + kk]);
            uint32_t a1 = cvt_tf32(xr_g[rowB + kk]);
            uint32_t a2 = cvt_tf32(xr_g[rowA + kk + 4]);
            uint32_t a3 = cvt_tf32(xr_g[rowB + kk + 4]);
            const int kc = ks*8 + 2*j;
            #pragma unroll
            for (int nt = 0; nt < 9; ++nt) {
                uint2 bb = *(const uint2*)&BRp[(nt*8 + q)*136 + kc];
                mma8(acc[nt], a0, a1, a2, a3, bb.x, bb.y);
            }
        }
        #pragma unroll 2
        for (int ks = 0; ks < 16; ++ks) {
            const int kk = ks*8 + j;
            uint32_t a0 = cvt_tf32(xi_g[rowA + kk]);
            uint32_t a1 = cvt_tf32(xi_g[rowB + kk]);
            uint32_t a2 = cvt_tf32(xi_g[rowA + kk + 4]);
            uint32_t a3 = cvt_tf32(xi_g[rowB + kk + 4]);
            const int kc = ks*8 + 2*j;
            #pragma unroll
            for (int nt = 0; nt < 9; ++nt) {
                uint2 bb = *(const uint2*)&BIp[(nt*8 + q)*136 + kc];
                uint32_t m = (nt < 8) ? 0x80000000u : 0u;   // -Bwi, but +dtw
                mma8(acc[nt], a0, a1, a2, a3, bb.x ^ m, bb.y ^ m);
            }
        }
        // ---- dt: shfl within warp, clamp, publish to smem ----
        const float db0 = dtb_g[0], db1 = dtb_g[1];
        const int src = l & ~3;
        float dmL = __shfl_sync(0xffffffffu, acc[8][0], src);
        float dpL = __shfl_sync(0xffffffffu, acc[8][1], src);
        float dmH = __shfl_sync(0xffffffffu, acc[8][2], src);
        float dpH = __shfl_sync(0xffffffffu, acc[8][3], src);
        dmL = clampdt(__expf(dmL + db0));  dpL = clampdt(__expf(dpL + db1));
        dmH = clampdt(__expf(dmH + db0));  dpH = clampdt(__expf(dpH + db1));
        if (j == 0) {
            dts[tokg*16 + q]     = make_float2(dmL, dpL);
            dts[tokg*16 + q + 8] = make_float2(dmH, dpH);
        }
    } else {
        // ---- imag pass: Bx_i ----
        #pragma unroll 2
        for (int ks = 0; ks < 16; ++ks) {
            const int kk = ks*8 + j;
            uint32_t a0 = cvt_tf32(xr_g[rowA + kk]);
            uint32_t a1 = cvt_tf32(xr_g[rowB + kk]);
            uint32_t a2 = cvt_tf32(xr_g[rowA + kk + 4]);
            uint32_t a3 = cvt_tf32(xr_g[rowB + kk + 4]);
            const int kc = ks*8 + 2*j;
            #pragma unroll
            for (int nt = 0; nt < 8; ++nt) {
                uint2 bb = *(const uint2*)&BIp[(nt*8 + q)*136 + kc];
                mma8(acc[nt], a0, a1, a2, a3, bb.x, bb.y);
            }
        }
        #pragma unroll 2
        for (int ks = 0; ks < 16; ++ks) {
            const int kk = ks*8 + j;
            uint32_t a0 = cvt_tf32(xi_g[rowA + kk]);
            uint32_t a1 = cvt_tf32(xi_g[rowB + kk]);
            uint32_t a2 = cvt_tf32(xi_g[rowA + kk + 4]);
            uint32_t a3 = cvt_tf32(xi_g[rowB + kk + 4]);
            const int kc = ks*8 + 2*j;
            #pragma unroll
            for (int nt = 0; nt < 8; ++nt) {
                uint2 bb = *(const uint2*)&BRp[(nt*8 + q)*136 + kc];
                mma8(acc[nt], a0, a1, a2, a3, bb.x, bb.y);
            }
        }
    }
    __syncthreads();

    // ---- epilogue (both halves) ----
    float2 dL = dts[tokg*16 + q];
    float2 dH = dts[tokg*16 + q + 8];
    const size_t idxL = ((size_t)(b*8 + q)*2048 + s0)*64;
    const size_t idxH = idxL + 64;
    float2* dst = pass ? g_abi : g_abr;

    #pragma unroll
    for (int nt = 0; nt < 8; ++nt) {
        int n0 = nt*8 + 2*j;
        float nl0 = nlA[q*64 + n0], nl1 = nlA[q*64 + n0 + 1];
        float ap0 = aph[q*64 + n0], ap1 = aph[q*64 + n0 + 1];
        float t0, t1;
        if (pass == 0) {
            t0 = pexp(dL.x*nl0) * pcos(dL.y*ap0);
            t1 = pexp(dL.x*nl1) * pcos(dL.y*ap1);
        } else {
            t0 = pexp(dL.x*nl0) * psin(dL.y*ap0);
            t1 = pexp(dL.x*nl1) * psin(dL.y*ap1);
        }
        *(float4*)&dst[idxL + n0] = make_float4(t0, acc[nt][0]*dL.x, t1, acc[nt][1]*dL.x);
        if (pass == 0) {
            t0 = pexp(dH.x*nl0) * pcos(dH.y*ap0);
            t1 = pexp(dH.x*nl1) * pcos(dH.y*ap1);
        } else {
            t0 = pexp(dH.x*nl0) * psin(dH.y*ap0);
            t1 = pexp(dH.x*nl1) * psin(dH.y*ap1);
        }
        *(float4*)&dst[idxH + n0] = make_float4(t0, acc[nt][2]*dH.x, t1, acc[nt][3]*dH.x);
    }
}

// ---------------------------------------------------------------------------
// Kernel 2a: per-subchunk (32 tokens) local scan from 0; store (h_local, c).
// ---------------------------------------------------------------------------
__global__ __launch_bounds__(64) void k2a_sub(void)
{
    int blk = blockIdx.x;                 // 0..2047
    int bg = blk >> 6, sub = blk & 63;
    int n = threadIdx.x;
    size_t base = ((size_t)bg*SS + sub*SUB)*NN + n;

    float hr = 0.f, hi = 0.f, cr = 1.f, ci = 0.f;
    float2 bufr[8], bufi[8];
    #pragma unroll
    for (int jj = 0; jj < 8; ++jj) {
        bufr[jj] = g_abr[base + (size_t)jj*NN];
        bufi[jj] = g_abi[base + (size_t)jj*NN];
    }

    #pragma unroll
    for (int t0 = 0; t0 < SUB; t0 += 8) {
        #pragma unroll
        for (int jj = 0; jj < 8; ++jj) {
            float ar = bufr[jj].x, br = bufr[jj].y;
            float ai = bufi[jj].x, bi = bufi[jj].y;
            int tn = t0 + 8 + jj;
            if (tn < SUB) {
                bufr[jj] = g_abr[base + (size_t)tn*NN];
                bufi[jj] = g_abi[base + (size_t)tn*NN];
            }
            float nr = fmaf(ar, hr, fmaf(-ai, hi, br));
            float ni = fmaf(ar, hi, fmaf( ai, hr, bi));
            hr = nr; hi = ni;
            float qr = ar*cr - ai*ci;
            float qi = ar*ci + ai*cr;
            cr = qr; ci = qi;
            g_hc[base + (size_t)(t0 + jj)*NN] = make_float4(hr, hi, cr, ci);
        }
    }
}

// ---------------------------------------------------------------------------
// Kernel 2b: sequential subchunk combine; renorm every 8th subchunk boundary.
// ---------------------------------------------------------------------------
__global__ __launch_bounds__(64) void k2b_combine(void)
{
    int bg = blockIdx.x;
    int n = threadIdx.x;
    float hr = 0.f, hi = 0.f;

    float4 ebuf[8];
    #pragma unroll
    for (int jj = 0; jj < 8; ++jj)
        ebuf[jj] = g_hc[((size_t)bg*SS + jj*SUB + 31)*NN + n];

    for (int s0 = 0; s0 < NSUB; s0 += 8) {
        #pragma unroll
        for (int jj = 0; jj < 8; ++jj) {
            float4 e = ebuf[jj];
            int nsub = s0 + 8 + jj;
            if (nsub < NSUB)
                ebuf[jj] = g_hc[((size_t)bg*SS + nsub*SUB + 31)*NN + n];
            int sub = s0 + jj;
            g_hin[(bg*NSUB + sub)*NN + n] = make_float2(hr, hi);
            float nr = fmaf(e.z, hr, fmaf(-e.w, hi, e.x));
            float ni = fmaf(e.z, hi, fmaf( e.w, hr, e.y));
            if ((sub & 7) == 7) {
                float nm = sqrtf(nr*nr + ni*ni + 1e-8f);
                float sc = fminf(nm, 100.0f)/nm;
                nr *= sc; ni *= sc;
            }
            hr = nr; hi = ni;
        }
    }
}

// ---------------------------------------------------------------------------
// Kernel 3: correction + tf32 MMA C-projection. CTA = 64 tokens, block = 512,
// 2 CTAs/SM. Warp task = (mpair 0..1: 32 tokens) x (nquad 0..3: 4 nt) x
// (half 0..1: yR/yI). Each B-fragment feeds 2 MMAs (32x32 warp tile) ->
// crossbar bytes/MMA 320 -> 256. Accumulators 2x4x4 = 32 floats.
// ---------------------------------------------------------------------------
__global__ __launch_bounds__(512, 2) void k3_mma(
    const float* __restrict__ Cwr, const float* __restrict__ Cwi,
    float* __restrict__ out)
{
    extern __shared__ float sm[];
    float* P  = sm;             // [128 d][72]  Cwr, k-pair packed
    float* Q  = P + 128*72;     // [128 d][72]  Cwi
    float* hs = Q + 128*72;     // [64 tok][136]  [hr | hi], k-pair packed

    const int tid = threadIdx.x;
    for (int idx = tid; idx < 128*72; idx += 512) {
        int d = idx / 72, c = idx - d*72;
        float vp = 0.f, vq = 0.f;
        if (c < 64) {
            int k = unpos(c);
            vp = Cwr[d*64 + k];
            vq = Cwi[d*64 + k];
        }
        P[idx] = tf32f(vp);
        Q[idx] = tf32f(vq);
    }

    // ---- correction prologue: 64 tok x 64 n ----
    const int tau_base = blockIdx.x*64;
    #pragma unroll
    for (int ii = 0; ii < 8; ++ii) {
        int cell = ii*512 + tid;
        int tl = cell >> 6, n = cell & 63;
        int tau = tau_base + tl;
        int b = tau >> 14, g = tau & 7, s = (tau >> 3) & 2047;
        int bg = b*8 + g;
        float4 hc = g_hc[((size_t)bg*2048 + s)*64 + n];
        float2 hin = g_hin[(bg*64 + (s >> 5))*64 + n];
        float hr = fmaf(hc.z, hin.x, fmaf(-hc.w, hin.y, hc.x));
        float hi = fmaf(hc.z, hin.y, fmaf( hc.w, hin.x, hc.y));
        if ((s & 255) == 255) {
            float nm = sqrtf(hr*hr + hi*hi + 1e-8f);
            float sc = fminf(nm, 100.0f)/nm;
            hr *= sc; hi *= sc;
        }
        int pos = posf(n);
        hs[tl*136 + pos]      = tf32f(hr);
        hs[tl*136 + 64 + pos] = tf32f(hi);
    }
    __syncthreads();

    const int w = tid >> 5, l = tid & 31;
    const int q = l >> 2, j = l & 3;
    const int mpair = w & 1;           // which 32-token block
    const int nquad = (w >> 1) & 3;    // which 4 nt-tiles
    const int half  = w >> 3;          // 0 = yR, 1 = yI
    const int row0 = mpair*32 + q;
    const int ntb = nquad*4;

    const float* Blo = half ? Q : P;     // k < 64
    const float* Bhi = half ? P : Q;     // k >= 64
    const uint32_t mhi = half ? 0u : 0x80000000u;   // negate Q for yR

    float y[2][4][4];
    #pragma unroll
    for (int m = 0; m < 2; ++m)
        #pragma unroll
        for (int t = 0; t < 4; ++t) { y[m][t][0]=0.f; y[m][t][1]=0.f; y[m][t][2]=0.f; y[m][t][3]=0.f; }

    // ---- hr half (k < 64) ----
    #pragma unroll
    for (int ks = 0; ks < 8; ++ks) {
        const int kc = ks*8 + 2*j;
        uint2 a00 = *(const uint2*)&hs[row0*136 + kc];
        uint2 a01 = *(const uint2*)&hs[(row0 + 8)*136 + kc];
        uint2 a10 = *(const uint2*)&hs[(row0 + 16)*136 + kc];
        uint2 a11 = *(const uint2*)&hs[(row0 + 24)*136 + kc];
        #pragma unroll
        for (int t = 0; t < 4; ++t) {
            uint2 bb = *(const uint2*)&Blo[((ntb + t)*8 + q)*72 + kc];
            mma8(y[0][t], a00.x, a01.x, a00.y, a01.y, bb.x, bb.y);
            mma8(y[1][t], a10.x, a11.x, a10.y, a11.y, bb.x, bb.y);
        }
    }
    // ---- hi half (k >= 64) ----
    #pragma unroll
    for (int ks = 0; ks < 8; ++ks) {
        const int kc = ks*8 + 2*j;
        uint2 a00 = *(const uint2*)&hs[row0*136 + 64 + kc];
        uint2 a01 = *(const uint2*)&hs[(row0 + 8)*136 + 64 + kc];
        uint2 a10 = *(const uint2*)&hs[(row0 + 16)*136 + 64 + kc];
        uint2 a11 = *(const uint2*)&hs[(row0 + 24)*136 + 64 + kc];
        #pragma unroll
        for (int t = 0; t < 4; ++t) {
            uint2 bb = *(const uint2*)&Bhi[((ntb + t)*8 + q)*72 + kc];
            mma8(y[0][t], a00.x, a01.x, a00.y, a01.y, bb.x ^ mhi, bb.y ^ mhi);
            mma8(y[1][t], a10.x, a11.x, a10.y, a11.y, bb.x ^ mhi, bb.y ^ mhi);
        }
    }

    // ---- output ----
    float* outh = out + (size_t)half * ((size_t)NTOK*128);
    #pragma unroll
    for (int t = 0; t < 4; ++t) {
        int d0 = (ntb + t)*8 + 2*j;
        size_t tA = (size_t)(tau_base + row0)*128 + d0;
        size_t tB = (size_t)(tau_base + row0 + 8)*128 + d0;
        size_t tC = (size_t)(tau_base + row0 + 16)*128 + d0;
        size_t tD = (size_t)(tau_base + row0 + 24)*128 + d0;
        *(float2*)&outh[tA] = make_float2(y[0][t][0], y[0][t][1]);
        *(float2*)&outh[tB] = make_float2(y[0][t][2], y[0][t][3]);
        *(float2*)&outh[tC] = make_float2(y[1][t][0], y[1][t][1]);
        *(float2*)&outh[tD] = make_float2(y[1][t][2], y[1][t][3]);
    }
}

// ---------------------------------------------------------------------------
extern "C" void kernel_launch(void* const* d_in, const int* in_sizes, int n_in,
                              void* d_out, int out_size)
{
    const float* x_r  = (const float*)d_in[0];
    const float* x_i  = (const float*)d_in[1];
    const float* logA = (const float*)d_in[2];
    const float* Aph  = (const float*)d_in[3];
    const float* Bwr  = (const float*)d_in[4];
    const float* Bwi  = (const float*)d_in[5];
    const float* Cwr  = (const float*)d_in[6];
    const float* Cwi  = (const float*)d_in[7];
    const float* dtw  = (const float*)d_in[8];
    const float* dtb  = (const float*)d_in[9];
    float* out = (float*)d_out;

    const int smem1 = (72*136*2 + 512*2 + 128*2) * 4;   // 83,456 B
    const int smem3 = (128*72*2 + 64*136) * 4;          // 108,544 B
    cudaFuncSetAttribute(k1_mma, cudaFuncAttributeMaxDynamicSharedMemorySize, smem1);
    cudaFuncSetAttribute(k3_mma, cudaFuncAttributeMaxDynamicSharedMemorySize, smem3);

    k1_mma<<<NTOK/128, 512, smem1>>>(x_r, x_i, logA, Aph, Bwr, Bwi, dtw, dtb);
    k2a_sub<<<BG*NSUB, 64>>>();
    k2b_combine<<<BG, 64>>>();
    k3_mma<<<NTOK/64, 512, smem3>>>(Cwr, Cwi, out);
}

// round 12
// speedup vs baseline: 1.0394x; 1.0394x over previous
#include <cuda_runtime.h>
#include <math.h>
#include <stdint.h>

// Fixed problem shapes
#define BB   4
#define SS   2048
#define GG   8
#define DD   128
#define NN   64
#define BG   (BB*GG)          // 32
#define NTOK (BB*SS*GG)       // 65536
#define SUB  16
#define NSUB (SS/SUB)         // 128

// Scratch (device globals; no allocation allowed)
__device__ float4 g_hc[BG*SS*NN];      // (hl_r, hl_i, c_r, c_i)  64 MB
__device__ float2 g_hin[BG*NSUB*NN];   // sub16 input states       2 MB

// ---------------- helpers ----------------
__device__ __forceinline__ uint32_t cvt_tf32(float f) {
    uint32_t u; asm("cvt.rna.tf32.f32 %0, %1;" : "=r"(u) : "f"(f)); return u;
}
__device__ __forceinline__ float tf32f(float f) {
    return __uint_as_float(cvt_tf32(f));
}
__device__ __forceinline__ void mma8(float* c, uint32_t a0, uint32_t a1,
                                     uint32_t a2, uint32_t a3,
                                     uint32_t b0, uint32_t b1) {
    asm("mma.sync.aligned.m16n8k8.row.col.f32.tf32.tf32.f32 "
        "{%0,%1,%2,%3}, {%4,%5,%6,%7}, {%8,%9}, {%0,%1,%2,%3};"
        : "+f"(c[0]), "+f"(c[1]), "+f"(c[2]), "+f"(c[3])
        : "r"(a0), "r"(a1), "r"(a2), "r"(a3), "r"(b0), "r"(b1));
}
__device__ __forceinline__ float clampdt(float v) {
    return fminf(fmaxf(v, 1e-4f), 2.0f);
}
// packed column position: pairs (k, k+4) adjacent for LDS.64 fragment loads
__device__ __forceinline__ int unpos(int c) {
    int slot = c & 7;
    return (c & ~7) + (slot >> 1) + ((slot & 1) << 2);
}
__device__ __forceinline__ int posf(int k) {
    return (k & ~7) + ((k & 3) << 1) + ((k & 4) >> 2);
}
// exp(z) on [-2.75, 0.05]: Taylor deg-10 about -1.375 (abs err < 1e-6)
__device__ __forceinline__ float pexp(float z) {
    const float t = z + 1.375f;
    float r = 6.96758145405495e-08f;
    r = fmaf(r, t, 6.96758145405495e-07f);
    r = fmaf(r, t, 6.27082330864946e-06f);
    r = fmaf(r, t, 5.01665864691957e-05f);
    r = fmaf(r, t, 3.51166105284370e-04f);
    r = fmaf(r, t, 2.10699663170622e-03f);
    r = fmaf(r, t, 1.05349831585311e-02f);
    r = fmaf(r, t, 4.21399326341243e-02f);
    r = fmaf(r, t, 1.26419797902373e-01f);
    r = fmaf(r, t, 2.52839595804746e-01f);
    r = fmaf(r, t, 2.52839595804746e-01f);
    return r;
}
// sin Taylor, |w| <= 2 (abs err < 2e-6)
__device__ __forceinline__ float psin(float w) {
    float w2 = w * w;
    float sr = -2.50521083854417e-08f;
    sr = fmaf(sr, w2, 2.75573192239859e-06f);
    sr = fmaf(sr, w2, -1.98412698412698e-04f);
    sr = fmaf(sr, w2, 8.33333333333333e-03f);
    sr = fmaf(sr, w2, -1.66666666666667e-01f);
    return fmaf(sr * w2, w, w);
}
// cos Taylor, |w| <= 2 (abs err < 2e-6)
__device__ __forceinline__ float pcos(float w) {
    float w2 = w * w;
    float cr = 2.08767569878681e-09f;
    cr = fmaf(cr, w2, -2.75573192239859e-07f);
    cr = fmaf(cr, w2, 2.48015873015873e-05f);
    cr = fmaf(cr, w2, -1.38888888888889e-03f);
    cr = fmaf(cr, w2, 4.16666666666667e-02f);
    cr = fmaf(cr, w2, -5.0e-01f);
    return fmaf(cr, w2, 1.0f);
}

// ---------------------------------------------------------------------------
// Kernel 1: tf32 MMA projection + in-warp 16-token affine scan.
// Warp = 16 CONSECUTIVE s of one (b,g). After the MMA epilogue each lane
// holds affine elements (a,b) for tokens q, q+8; a Hillis-Steele shfl scan
// over tokens produces (h_local, cumprod) directly -> writes g_hc.
// ---------------------------------------------------------------------------
__global__ __launch_bounds__(256, 2) void k1_mma(
    const float* __restrict__ xr_g, const float* __restrict__ xi_g,
    const float* __restrict__ logA, const float* __restrict__ Aph_g,
    const float* __restrict__ Bwr,  const float* __restrict__ Bwi,
    const float* __restrict__ dtw_g, const float* __restrict__ dtb_g)
{
    extern __shared__ float sm[];
    float* BRp = sm;                 // [72][136]
    float* BIp = BRp + 72*136;       // [72][136]
    float* nlA = BIp + 72*136;       // [512]
    float* aph = nlA + 512;          // [512]

    const int tid = threadIdx.x;
    for (int idx = tid; idx < 72*136; idx += 256) {
        int r = idx / 136, c = idx - r*136;
        float vr = 0.f, vi = 0.f;
        if (c < 128 && r < 66) {
            int k = unpos(c);
            if (r < 64)      { vr = Bwr[r*128 + k];   vi = Bwi[r*128 + k]; }
            else if (r == 64){ vr = dtw_g[k];         vi = dtw_g[128 + k]; }
            else             { vr = dtw_g[256 + k];   vi = dtw_g[384 + k]; }
        }
        BRp[idx] = tf32f(vr);
        BIp[idx] = tf32f(vi);
    }
    for (int i = tid; i < 512; i += 256) {
        nlA[i] = -log1pf(expf(logA[i]));   // -softplus
        aph[i] = Aph_g[i];
    }
    __syncthreads();

    const int w = tid >> 5, l = tid & 31;
    const int q = l >> 2, j = l & 3;
    const int slice = blockIdx.x*8 + w;     // 0..4095
    const int bg = slice >> 7, s16 = slice & 127;
    const int b = bg >> 3, g = bg & 7;
    const int g6 = g*64;

    float cr[9][4], ci[8][4];
    #pragma unroll
    for (int t = 0; t < 9; ++t) { cr[t][0]=0.f; cr[t][1]=0.f; cr[t][2]=0.f; cr[t][3]=0.f; }
    #pragma unroll
    for (int t = 0; t < 8; ++t) { ci[t][0]=0.f; ci[t][1]=0.f; ci[t][2]=0.f; ci[t][3]=0.f; }

    // A rows: token (b, s16*16 + r, g); row r=q and r=q+8. s-step = 1024 floats.
    const size_t rowA = (size_t)((b*2048 + s16*16 + q)*8 + g)*128;
    const size_t rowB = rowA + (size_t)8*1024;

    // ---- xr half: Bx_r += xr*Bwr ; Bx_i += xr*Bwi ; dt += xr*dtw[:,k<128]
    #pragma unroll 2
    for (int ks = 0; ks < 16; ++ks) {
        const int kk = ks*8 + j;
        uint32_t a0 = cvt_tf32(xr_g[rowA + kk]);
        uint32_t a1 = cvt_tf32(xr_g[rowB + kk]);
        uint32_t a2 = cvt_tf32(xr_g[rowA + kk + 4]);
        uint32_t a3 = cvt_tf32(xr_g[rowB + kk + 4]);
        const int kc = ks*8 + 2*j;
        #pragma unroll
        for (int nt = 0; nt < 9; ++nt) {
            uint2 bb = *(const uint2*)&BRp[(nt*8 + q)*136 + kc];
            mma8(cr[nt], a0, a1, a2, a3, bb.x, bb.y);
        }
        #pragma unroll
        for (int nt = 0; nt < 8; ++nt) {
            uint2 bb = *(const uint2*)&BIp[(nt*8 + q)*136 + kc];
            mma8(ci[nt], a0, a1, a2, a3, bb.x, bb.y);
        }
    }
    // ---- xi half: Bx_r -= xi*Bwi ; Bx_i += xi*Bwr ; dt += xi*dtw[:,k>=128]
    #pragma unroll 2
    for (int ks = 0; ks < 16; ++ks) {
        const int kk = ks*8 + j;
        uint32_t a0 = cvt_tf32(xi_g[rowA + kk]);
        uint32_t a1 = cvt_tf32(xi_g[rowB + kk]);
        uint32_t a2 = cvt_tf32(xi_g[rowA + kk + 4]);
        uint32_t a3 = cvt_tf32(xi_g[rowB + kk + 4]);
        const int kc = ks*8 + 2*j;
        #pragma unroll
        for (int nt = 0; nt < 9; ++nt) {
            uint2 bb = *(const uint2*)&BIp[(nt*8 + q)*136 + kc];
            uint32_t m = (nt < 8) ? 0x80000000u : 0u;   // -Bwi, but +dtw
            mma8(cr[nt], a0, a1, a2, a3, bb.x ^ m, bb.y ^ m);
        }
        #pragma unroll
        for (int nt = 0; nt < 8; ++nt) {
            uint2 bb = *(const uint2*)&BRp[(nt*8 + q)*136 + kc];
            mma8(ci[nt], a0, a1, a2, a3, bb.x, bb.y);
        }
    }

    // ---- dt via shfl, clamp ----
    const float db0 = dtb_g[0], db1 = dtb_g[1];
    const int src = l & ~3;   // lane with j==0 in this q-group
    float dmL = __shfl_sync(0xffffffffu, cr[8][0], src);
    float dpL = __shfl_sync(0xffffffffu, cr[8][1], src);
    float dmH = __shfl_sync(0xffffffffu, cr[8][2], src);
    float dpH = __shfl_sync(0xffffffffu, cr[8][3], src);
    dmL = clampdt(__expf(dmL + db0));  dpL = clampdt(__expf(dpL + db1));
    dmH = clampdt(__expf(dmH + db0));  dpH = clampdt(__expf(dpH + db1));

    // ---- per-n: build affine elements, 16-token shfl scan, write (h, c) ----
    const size_t idxL = ((size_t)bg*2048 + s16*16 + q)*64;
    const size_t idxH = idxL + (size_t)8*64;

    #pragma unroll
    for (int nt = 0; nt < 8; ++nt) {
        #pragma unroll
        for (int e = 0; e < 2; ++e) {
            const int n = nt*8 + 2*j + e;
            const float nl = nlA[g6 + n], ap = aph[g6 + n];
            // element for token q (L) and token q+8 (H)
            float amL = pexp(dmL*nl);
            float aLr = amL*pcos(dpL*ap), aLi = amL*psin(dpL*ap);
            float bLr = cr[nt][e]*dmL,    bLi = ci[nt][e]*dmL;
            float amH = pexp(dmH*nl);
            float aHr = amH*pcos(dpH*ap), aHi = amH*psin(dpH*ap);
            float bHr = cr[nt][2+e]*dmH,  bHi = ci[nt][2+e]*dmH;

            // Hillis-Steele over q (both halves simultaneously)
            #pragma unroll
            for (int st = 1; st <= 4; st <<= 1) {
                const int dlt = 4*st;
                float par = __shfl_up_sync(0xffffffffu, aLr, dlt);
                float pai = __shfl_up_sync(0xffffffffu, aLi, dlt);
                float pbr = __shfl_up_sync(0xffffffffu, bLr, dlt);
                float pbi = __shfl_up_sync(0xffffffffu, bLi, dlt);
                float qar = __shfl_up_sync(0xffffffffu, aHr, dlt);
                float qai = __shfl_up_sync(0xffffffffu, aHi, dlt);
                float qbr = __shfl_up_sync(0xffffffffu, bHr, dlt);
                float qbi = __shfl_up_sync(0xffffffffu, bHi, dlt);
                if (q >= st) {
                    float t1 = aLr*par - aLi*pai;
                    float t2 = aLr*pai + aLi*par;
                    float t3 = fmaf(aLr, pbr, fmaf(-aLi, pbi, bLr));
                    float t4 = fmaf(aLr, pbi, fmaf( aLi, pbr, bLi));
                    aLr = t1; aLi = t2; bLr = t3; bLi = t4;
                    t1 = aHr*qar - aHi*qai;
                    t2 = aHr*qai + aHi*qar;
                    t3 = fmaf(aHr, qbr, fmaf(-aHi, qbi, bHr));
                    t4 = fmaf(aHr, qbi, fmaf( aHi, qbr, bHi));
                    aHr = t1; aHi = t2; bHr = t3; bHi = t4;
                }
            }
            // bridge: full prefix of tokens 0..7 lives at q==7 (lane 28+j)
            float f7ar = __shfl_sync(0xffffffffu, aLr, 28 + j);
            float f7ai = __shfl_sync(0xffffffffu, aLi, 28 + j);
            float f7br = __shfl_sync(0xffffffffu, bLr, 28 + j);
            float f7bi = __shfl_sync(0xffffffffu, bLi, 28 + j);
            float Har = aHr*f7ar - aHi*f7ai;
            float Hai = aHr*f7ai + aHi*f7ar;
            float Hbr = fmaf(aHr, f7br, fmaf(-aHi, f7bi, bHr));
            float Hbi = fmaf(aHr, f7bi, fmaf( aHi, f7br, bHi));

            g_hc[idxL + n] = make_float4(bLr, bLi, aLr, aLi);   // (h, c) token q
            g_hc[idxH + n] = make_float4(Hbr, Hbi, Har, Hai);   // token q+8
        }
    }
}

// ---------------------------------------------------------------------------
// Kernel 2b: sequential sub16 combine; renorm every 16th sub16 boundary.
// ---------------------------------------------------------------------------
__global__ __launch_bounds__(64) void k2b_combine(void)
{
    int bg = blockIdx.x;
    int n = threadIdx.x;
    float hr = 0.f, hi = 0.f;

    float4 ebuf[8];
    #pragma unroll
    for (int jj = 0; jj < 8; ++jj)
        ebuf[jj] = g_hc[((size_t)bg*SS + jj*SUB + 15)*NN + n];

    for (int s0 = 0; s0 < NSUB; s0 += 8) {
        #pragma unroll
        for (int jj = 0; jj < 8; ++jj) {
            float4 e = ebuf[jj];
            int nsub = s0 + 8 + jj;
            if (nsub < NSUB)
                ebuf[jj] = g_hc[((size_t)bg*SS + nsub*SUB + 15)*NN + n];
            int sub = s0 + jj;
            g_hin[(bg*NSUB + sub)*NN + n] = make_float2(hr, hi);
            float nr = fmaf(e.z, hr, fmaf(-e.w, hi, e.x));
            float ni = fmaf(e.z, hi, fmaf( e.w, hr, e.y));
            if ((sub & 15) == 15) {
                float nm = sqrtf(nr*nr + ni*ni + 1e-8f);
                float sc = fminf(nm, 100.0f)/nm;
                nr *= sc; ni *= sc;
            }
            hr = nr; hi = ni;
        }
    }
}

// ---------------------------------------------------------------------------
// Kernel 3 (R10 winner): correction + tf32 MMA C-projection. CTA = 64 tokens,
// block 512, 2 CTAs/SM. Warp task = (mrow 0..3) x (nhalf 0..1) x (half 0..1).
// ---------------------------------------------------------------------------
__global__ __launch_bounds__(512, 2) void k3_mma(
    const float* __restrict__ Cwr, const float* __restrict__ Cwi,
    float* __restrict__ out)
{
    extern __shared__ float sm[];
    float* P  = sm;             // [128 d][72]  Cwr, k-pair packed
    float* Q  = P + 128*72;     // [128 d][72]  Cwi
    float* hs = Q + 128*72;     // [64 tok][136]  [hr | hi], k-pair packed

    const int tid = threadIdx.x;
    for (int idx = tid; idx < 128*72; idx += 512) {
        int d = idx / 72, c = idx - d*72;
        float vp = 0.f, vq = 0.f;
        if (c < 64) {
            int k = unpos(c);
            vp = Cwr[d*64 + k];
            vq = Cwi[d*64 + k];
        }
        P[idx] = tf32f(vp);
        Q[idx] = tf32f(vq);
    }

    // ---- correction prologue: 64 tok x 64 n ----
    const int tau_base = blockIdx.x*64;
    #pragma unroll
    for (int ii = 0; ii < 8; ++ii) {
        int cell = ii*512 + tid;
        int tl = cell >> 6, n = cell & 63;
        int tau = tau_base + tl;
        int b = tau >> 14, g = tau & 7, s = (tau >> 3) & 2047;
        int bg = b*8 + g;
        float4 hc = g_hc[((size_t)bg*2048 + s)*64 + n];
        float2 hin = g_hin[(bg*NSUB + (s >> 4))*64 + n];
        float hr = fmaf(hc.z, hin.x, fmaf(-hc.w, hin.y, hc.x));
        float hi = fmaf(hc.z, hin.y, fmaf( hc.w, hin.x, hc.y));
        if ((s & 255) == 255) {
            float nm = sqrtf(hr*hr + hi*hi + 1e-8f);
            float sc = fminf(nm, 100.0f)/nm;
            hr *= sc; hi *= sc;
        }
        int pos = posf(n);
        hs[tl*136 + pos]      = tf32f(hr);
        hs[tl*136 + 64 + pos] = tf32f(hi);
    }
    __syncthreads();

    const int w = tid >> 5, l = tid & 31;
    const int q = l >> 2, j = l & 3;
    const int mrow  = w & 3;           // which 16-token block
    const int nhalf = (w >> 2) & 1;    // which 8 nt-tiles
    const int half  = w >> 3;          // 0 = yR, 1 = yI
    const int row0 = mrow*16 + q;
    const int ntb = nhalf*8;

    const float* Blo = half ? Q : P;     // k < 64
    const float* Bhi = half ? P : Q;     // k >= 64
    const uint32_t mhi = half ? 0u : 0x80000000u;   // negate Q for yR

    float y[8][4];
    #pragma unroll
    for (int t = 0; t < 8; ++t) { y[t][0]=0.f; y[t][1]=0.f; y[t][2]=0.f; y[t][3]=0.f; }

    // ---- hr half (k < 64) ----
    #pragma unroll
    for (int ks = 0; ks < 8; ++ks) {
        const int kc = ks*8 + 2*j;
        uint2 aa0 = *(const uint2*)&hs[row0*136 + kc];
        uint2 aa1 = *(const uint2*)&hs[(row0 + 8)*136 + kc];
        #pragma unroll
        for (int t = 0; t < 8; ++t) {
            uint2 bb = *(const uint2*)&Blo[((ntb + t)*8 + q)*72 + kc];
            mma8(y[t], aa0.x, aa1.x, aa0.y, aa1.y, bb.x, bb.y);
        }
    }
    // ---- hi half (k >= 64) ----
    #pragma unroll
    for (int ks = 0; ks < 8; ++ks) {
        const int kc = ks*8 + 2*j;
        uint2 aa0 = *(const uint2*)&hs[row0*136 + 64 + kc];
        uint2 aa1 = *(const uint2*)&hs[(row0 + 8)*136 + 64 + kc];
        #pragma unroll
        for (int t = 0; t < 8; ++t) {
            uint2 bb = *(const uint2*)&Bhi[((ntb + t)*8 + q)*72 + kc];
            mma8(y[t], aa0.x, aa1.x, aa0.y, aa1.y, bb.x ^ mhi, bb.y ^ mhi);
        }
    }

    // ---- output ----
    float* outh = out + (size_t)half * ((size_t)NTOK*128);
    #pragma unroll
    for (int t = 0; t < 8; ++t) {
        int d0 = (ntb + t)*8 + 2*j;
        size_t tA = (size_t)(tau_base + row0)*128 + d0;
        size_t tB = (size_t)(tau_base + row0 + 8)*128 + d0;
        *(float2*)&outh[tA] = make_float2(y[t][0], y[t][1]);
        *(float2*)&outh[tB] = make_float2(y[t][2], y[t][3]);
    }
}

// ---------------------------------------------------------------------------
extern "C" void kernel_launch(void* const* d_in, const int* in_sizes, int n_in,
                              void* d_out, int out_size)
{
    const float* x_r  = (const float*)d_in[0];
    const float* x_i  = (const float*)d_in[1];
    const float* logA = (const float*)d_in[2];
    const float* Aph  = (const float*)d_in[3];
    const float* Bwr  = (const float*)d_in[4];
    const float* Bwi  = (const float*)d_in[5];
    const float* Cwr  = (const float*)d_in[6];
    const float* Cwi  = (const float*)d_in[7];
    const float* dtw  = (const float*)d_in[8];
    const float* dtb  = (const float*)d_in[9];
    float* out = (float*)d_out;

    const int smem1 = (72*136*2 + 1024) * 4;          // 82,432 B
    const int smem3 = (128*72*2 + 64*136) * 4;        // 108,544 B
    cudaFuncSetAttribute(k1_mma, cudaFuncAttributeMaxDynamicSharedMemorySize, smem1);
    cudaFuncSetAttribute(k3_mma, cudaFuncAttributeMaxDynamicSharedMemorySize, smem3);

    k1_mma<<<512, 256, smem1>>>(x_r, x_i, logA, Aph, Bwr, Bwi, dtw, dtb);
    k2b_combine<<<BG, 64>>>();
    k3_mma<<<NTOK/64, 512, smem3>>>(Cwr, Cwi, out);
}

// round 13
// speedup vs baseline: 1.2176x; 1.1714x over previous
#include <cuda_runtime.h>
#include <math.h>
#include <stdint.h>

// Fixed problem shapes
#define BB   4
#define SS   2048
#define GG   8
#define DD   128
#define NN   64
#define BG   (BB*GG)          // 32
#define NTOK (BB*SS*GG)       // 65536
#define SUB  16
#define NSUB (SS/SUB)         // 128

// Scratch (device globals; no allocation allowed)
__device__ float4 g_hc[BG*SS*NN];      // (hl_r, hl_i, c_r, c_i)  64 MB
__device__ float2 g_hin[BG*NSUB*NN];   // sub16 input states       2 MB

// ---------------- helpers ----------------
__device__ __forceinline__ uint32_t cvt_tf32(float f) {
    uint32_t u; asm("cvt.rna.tf32.f32 %0, %1;" : "=r"(u) : "f"(f)); return u;
}
__device__ __forceinline__ float tf32f(float f) {
    return __uint_as_float(cvt_tf32(f));
}
__device__ __forceinline__ void mma8(float* c, uint32_t a0, uint32_t a1,
                                     uint32_t a2, uint32_t a3,
                                     uint32_t b0, uint32_t b1) {
    asm("mma.sync.aligned.m16n8k8.row.col.f32.tf32.tf32.f32 "
        "{%0,%1,%2,%3}, {%4,%5,%6,%7}, {%8,%9}, {%0,%1,%2,%3};"
        : "+f"(c[0]), "+f"(c[1]), "+f"(c[2]), "+f"(c[3])
        : "r"(a0), "r"(a1), "r"(a2), "r"(a3), "r"(b0), "r"(b1));
}
__device__ __forceinline__ float clampdt(float v) {
    return fminf(fmaxf(v, 1e-4f), 2.0f);
}
// packed column position: pairs (k, k+4) adjacent for LDS.64 fragment loads
__device__ __forceinline__ int unpos(int c) {
    int slot = c & 7;
    return (c & ~7) + (slot >> 1) + ((slot & 1) << 2);
}
__device__ __forceinline__ int posf(int k) {
    return (k & ~7) + ((k & 3) << 1) + ((k & 4) >> 2);
}

// ---------------------------------------------------------------------------
// Kernel 1: tf32 MMA projection + in-warp 16-token affine scan. Persistent
// (grid 296), weights fill amortized. Epilogue uses MUFU (__expf/__sincosf).
// ---------------------------------------------------------------------------
__global__ __launch_bounds__(256, 2) void k1_mma(
    const float* __restrict__ xr_g, const float* __restrict__ xi_g,
    const float* __restrict__ logA, const float* __restrict__ Aph_g,
    const float* __restrict__ Bwr,  const float* __restrict__ Bwi,
    const float* __restrict__ dtw_g, const float* __restrict__ dtb_g)
{
    extern __shared__ float sm[];
    float* BRp = sm;                 // [72][136]
    float* BIp = BRp + 72*136;       // [72][136]
    float* nlA = BIp + 72*136;       // [512]
    float* aph = nlA + 512;          // [512]

    const int tid = threadIdx.x;
    for (int idx = tid; idx < 72*136; idx += 256) {
        int r = idx / 136, c = idx - r*136;
        float vr = 0.f, vi = 0.f;
        if (c < 128 && r < 66) {
            int k = unpos(c);
            if (r < 64)      { vr = Bwr[r*128 + k];   vi = Bwi[r*128 + k]; }
            else if (r == 64){ vr = dtw_g[k];         vi = dtw_g[128 + k]; }
            else             { vr = dtw_g[256 + k];   vi = dtw_g[384 + k]; }
        }
        BRp[idx] = tf32f(vr);
        BIp[idx] = tf32f(vi);
    }
    for (int i = tid; i < 512; i += 256) {
        nlA[i] = -log1pf(expf(logA[i]));   // -softplus
        aph[i] = Aph_g[i];
    }
    __syncthreads();

    const int w = tid >> 5, l = tid & 31;
    const int q = l >> 2, j = l & 3;
    const float db0 = dtb_g[0], db1 = dtb_g[1];

    for (int grp = blockIdx.x; grp < 512; grp += gridDim.x) {
        const int slice = grp*8 + w;          // 0..4095
        const int bg = slice >> 7, s16 = slice & 127;
        const int b = bg >> 3, g = bg & 7;
        const int g6 = g*64;

        float cr[9][4], ci[8][4];
        #pragma unroll
        for (int t = 0; t < 9; ++t) { cr[t][0]=0.f; cr[t][1]=0.f; cr[t][2]=0.f; cr[t][3]=0.f; }
        #pragma unroll
        for (int t = 0; t < 8; ++t) { ci[t][0]=0.f; ci[t][1]=0.f; ci[t][2]=0.f; ci[t][3]=0.f; }

        const size_t rowA = (size_t)((b*2048 + s16*16 + q)*8 + g)*128;
        const size_t rowB = rowA + (size_t)8*1024;

        // ---- xr half ----
        #pragma unroll 2
        for (int ks = 0; ks < 16; ++ks) {
            const int kk = ks*8 + j;
            uint32_t a0 = cvt_tf32(xr_g[rowA + kk]);
            uint32_t a1 = cvt_tf32(xr_g[rowB + kk]);
            uint32_t a2 = cvt_tf32(xr_g[rowA + kk + 4]);
            uint32_t a3 = cvt_tf32(xr_g[rowB + kk + 4]);
            const int kc = ks*8 + 2*j;
            #pragma unroll
            for (int nt = 0; nt < 9; ++nt) {
                uint2 bb = *(const uint2*)&BRp[(nt*8 + q)*136 + kc];
                mma8(cr[nt], a0, a1, a2, a3, bb.x, bb.y);
            }
            #pragma unroll
            for (int nt = 0; nt < 8; ++nt) {
                uint2 bb = *(const uint2*)&BIp[(nt*8 + q)*136 + kc];
                mma8(ci[nt], a0, a1, a2, a3, bb.x, bb.y);
            }
        }
        // ---- xi half ----
        #pragma unroll 2
        for (int ks = 0; ks < 16; ++ks) {
            const int kk = ks*8 + j;
            uint32_t a0 = cvt_tf32(xi_g[rowA + kk]);
            uint32_t a1 = cvt_tf32(xi_g[rowB + kk]);
            uint32_t a2 = cvt_tf32(xi_g[rowA + kk + 4]);
            uint32_t a3 = cvt_tf32(xi_g[rowB + kk + 4]);
            const int kc = ks*8 + 2*j;
            #pragma unroll
            for (int nt = 0; nt < 9; ++nt) {
                uint2 bb = *(const uint2*)&BIp[(nt*8 + q)*136 + kc];
                uint32_t m = (nt < 8) ? 0x80000000u : 0u;   // -Bwi, but +dtw
                mma8(cr[nt], a0, a1, a2, a3, bb.x ^ m, bb.y ^ m);
            }
            #pragma unroll
            for (int nt = 0; nt < 8; ++nt) {
                uint2 bb = *(const uint2*)&BRp[(nt*8 + q)*136 + kc];
                mma8(ci[nt], a0, a1, a2, a3, bb.x, bb.y);
            }
        }

        // ---- dt via shfl, clamp ----
        const int src = l & ~3;
        float dmL = __shfl_sync(0xffffffffu, cr[8][0], src);
        float dpL = __shfl_sync(0xffffffffu, cr[8][1], src);
        float dmH = __shfl_sync(0xffffffffu, cr[8][2], src);
        float dpH = __shfl_sync(0xffffffffu, cr[8][3], src);
        dmL = clampdt(__expf(dmL + db0));  dpL = clampdt(__expf(dpL + db1));
        dmH = clampdt(__expf(dmH + db0));  dpH = clampdt(__expf(dpH + db1));

        // ---- per-n: affine elements (MUFU), 16-token shfl scan, write ----
        const size_t idxL = ((size_t)bg*2048 + s16*16 + q)*64;
        const size_t idxH = idxL + (size_t)8*64;

        #pragma unroll
        for (int nt = 0; nt < 8; ++nt) {
            #pragma unroll
            for (int e = 0; e < 2; ++e) {
                const int n = nt*8 + 2*j + e;
                const float nl = nlA[g6 + n], ap = aph[g6 + n];
                float snL, csL, snH, csH;
                float amL = __expf(dmL*nl);
                __sincosf(dpL*ap, &snL, &csL);
                float aLr = amL*csL, aLi = amL*snL;
                float bLr = cr[nt][e]*dmL, bLi = ci[nt][e]*dmL;
                float amH = __expf(dmH*nl);
                __sincosf(dpH*ap, &snH, &csH);
                float aHr = amH*csH, aHi = amH*snH;
                float bHr = cr[nt][2+e]*dmH, bHi = ci[nt][2+e]*dmH;

                // Hillis-Steele over q (both halves simultaneously)
                #pragma unroll
                for (int st = 1; st <= 4; st <<= 1) {
                    const int dlt = 4*st;
                    float par = __shfl_up_sync(0xffffffffu, aLr, dlt);
                    float pai = __shfl_up_sync(0xffffffffu, aLi, dlt);
                    float pbr = __shfl_up_sync(0xffffffffu, bLr, dlt);
                    float pbi = __shfl_up_sync(0xffffffffu, bLi, dlt);
                    float qar = __shfl_up_sync(0xffffffffu, aHr, dlt);
                    float qai = __shfl_up_sync(0xffffffffu, aHi, dlt);
                    float qbr = __shfl_up_sync(0xffffffffu, bHr, dlt);
                    float qbi = __shfl_up_sync(0xffffffffu, bHi, dlt);
                    if (q >= st) {
                        float t1 = aLr*par - aLi*pai;
                        float t2 = aLr*pai + aLi*par;
                        float t3 = fmaf(aLr, pbr, fmaf(-aLi, pbi, bLr));
                        float t4 = fmaf(aLr, pbi, fmaf( aLi, pbr, bLi));
                        aLr = t1; aLi = t2; bLr = t3; bLi = t4;
                        t1 = aHr*qar - aHi*qai;
                        t2 = aHr*qai + aHi*qar;
                        t3 = fmaf(aHr, qbr, fmaf(-aHi, qbi, bHr));
                        t4 = fmaf(aHr, qbi, fmaf( aHi, qbr, bHi));
                        aHr = t1; aHi = t2; bHr = t3; bHi = t4;
                    }
                }
                // bridge: full prefix of tokens 0..7 lives at q==7 (lane 28+j)
                float f7ar = __shfl_sync(0xffffffffu, aLr, 28 + j);
                float f7ai = __shfl_sync(0xffffffffu, aLi, 28 + j);
                float f7br = __shfl_sync(0xffffffffu, bLr, 28 + j);
                float f7bi = __shfl_sync(0xffffffffu, bLi, 28 + j);
                float Har = aHr*f7ar - aHi*f7ai;
                float Hai = aHr*f7ai + aHi*f7ar;
                float Hbr = fmaf(aHr, f7br, fmaf(-aHi, f7bi, bHr));
                float Hbi = fmaf(aHr, f7bi, fmaf( aHi, f7br, bHi));

                g_hc[idxL + n] = make_float4(bLr, bLi, aLr, aLi);   // token q
                g_hc[idxH + n] = make_float4(Hbr, Hbi, Har, Hai);   // token q+8
            }
        }
    }
}

// ---------------------------------------------------------------------------
// Kernel 2b: sequential sub16 combine; renorm every 16th sub16 boundary.
// ---------------------------------------------------------------------------
__global__ __launch_bounds__(64) void k2b_combine(void)
{
    int bg = blockIdx.x;
    int n = threadIdx.x;
    float hr = 0.f, hi = 0.f;

    float4 ebuf[8];
    #pragma unroll
    for (int jj = 0; jj < 8; ++jj)
        ebuf[jj] = g_hc[((size_t)bg*SS + jj*SUB + 15)*NN + n];

    for (int s0 = 0; s0 < NSUB; s0 += 8) {
        #pragma unroll
        for (int jj = 0; jj < 8; ++jj) {
            float4 e = ebuf[jj];
            int nsub = s0 + 8 + jj;
            if (nsub < NSUB)
                ebuf[jj] = g_hc[((size_t)bg*SS + nsub*SUB + 15)*NN + n];
            int sub = s0 + jj;
            g_hin[(bg*NSUB + sub)*NN + n] = make_float2(hr, hi);
            float nr = fmaf(e.z, hr, fmaf(-e.w, hi, e.x));
            float ni = fmaf(e.z, hi, fmaf( e.w, hr, e.y));
            if ((sub & 15) == 15) {
                float nm = sqrtf(nr*nr + ni*ni + 1e-8f);
                float sc = fminf(nm, 100.0f)/nm;
                nr *= sc; ni *= sc;
            }
            hr = nr; hi = ni;
        }
    }
}

// ---------------------------------------------------------------------------
// Kernel 3: correction + tf32 MMA C-projection. Persistent (grid 296),
// CTA tile = 64 tokens, block 512, 2 CTAs/SM; P/Q fill amortized.
// ---------------------------------------------------------------------------
__global__ __launch_bounds__(512, 2) void k3_mma(
    const float* __restrict__ Cwr, const float* __restrict__ Cwi,
    float* __restrict__ out)
{
    extern __shared__ float sm[];
    float* P  = sm;             // [128 d][72]  Cwr, k-pair packed
    float* Q  = P + 128*72;     // [128 d][72]  Cwi
    float* hs = Q + 128*72;     // [64 tok][136]  [hr | hi], k-pair packed

    const int tid = threadIdx.x;
    for (int idx = tid; idx < 128*72; idx += 512) {
        int d = idx / 72, c = idx - d*72;
        float vp = 0.f, vq = 0.f;
        if (c < 64) {
            int k = unpos(c);
            vp = Cwr[d*64 + k];
            vq = Cwi[d*64 + k];
        }
        P[idx] = tf32f(vp);
        Q[idx] = tf32f(vq);
    }

    const int w = tid >> 5, l = tid & 31;
    const int q = l >> 2, j = l & 3;
    const int mrow  = w & 3;           // which 16-token block
    const int nhalf = (w >> 2) & 1;    // which 8 nt-tiles
    const int half  = w >> 3;          // 0 = yR, 1 = yI
    const int row0 = mrow*16 + q;
    const int ntb = nhalf*8;

    const float* Blo = half ? Q : P;     // k < 64
    const float* Bhi = half ? P : Q;     // k >= 64
    const uint32_t mhi = half ? 0u : 0x80000000u;   // negate Q for yR
    float* outh = out + (size_t)half * ((size_t)NTOK*128);

    for (int tile = blockIdx.x; tile < NTOK/64; tile += gridDim.x) {
        const int tau_base = tile*64;

        // ---- correction prologue: 64 tok x 64 n ----
        #pragma unroll
        for (int ii = 0; ii < 8; ++ii) {
            int cell = ii*512 + tid;
            int tl = cell >> 6, n = cell & 63;
            int tau = tau_base + tl;
            int b = tau >> 14, g = tau & 7, s = (tau >> 3) & 2047;
            int bg = b*8 + g;
            float4 hc = g_hc[((size_t)bg*2048 + s)*64 + n];
            float2 hin = g_hin[(bg*NSUB + (s >> 4))*64 + n];
            float hr = fmaf(hc.z, hin.x, fmaf(-hc.w, hin.y, hc.x));
            float hi = fmaf(hc.z, hin.y, fmaf( hc.w, hin.x, hc.y));
            if ((s & 255) == 255) {
                float nm = sqrtf(hr*hr + hi*hi + 1e-8f);
                float sc = fminf(nm, 100.0f)/nm;
                hr *= sc; hi *= sc;
            }
            int pos = posf(n);
            hs[tl*136 + pos]      = tf32f(hr);
            hs[tl*136 + 64 + pos] = tf32f(hi);
        }
        __syncthreads();

        float y[8][4];
        #pragma unroll
        for (int t = 0; t < 8; ++t) { y[t][0]=0.f; y[t][1]=0.f; y[t][2]=0.f; y[t][3]=0.f; }

        // ---- hr half (k < 64) ----
        #pragma unroll
        for (int ks = 0; ks < 8; ++ks) {
            const int kc = ks*8 + 2*j;
            uint2 aa0 = *(const uint2*)&hs[row0*136 + kc];
            uint2 aa1 = *(const uint2*)&hs[(row0 + 8)*136 + kc];
            #pragma unroll
            for (int t = 0; t < 8; ++t) {
                uint2 bb = *(const uint2*)&Blo[((ntb + t)*8 + q)*72 + kc];
                mma8(y[t], aa0.x, aa1.x, aa0.y, aa1.y, bb.x, bb.y);
            }
        }
        // ---- hi half (k >= 64) ----
        #pragma unroll
        for (int ks = 0; ks < 8; ++ks) {
            const int kc = ks*8 + 2*j;
            uint2 aa0 = *(const uint2*)&hs[row0*136 + 64 + kc];
            uint2 aa1 = *(const uint2*)&hs[(row0 + 8)*136 + 64 + kc];
            #pragma unroll
            for (int t = 0; t < 8; ++t) {
                uint2 bb = *(const uint2*)&Bhi[((ntb + t)*8 + q)*72 + kc];
                mma8(y[t], aa0.x, aa1.x, aa0.y, aa1.y, bb.x ^ mhi, bb.y ^ mhi);
            }
        }

        // ---- output ----
        #pragma unroll
        for (int t = 0; t < 8; ++t) {
            int d0 = (ntb + t)*8 + 2*j;
            size_t tA = (size_t)(tau_base + row0)*128 + d0;
            size_t tB = (size_t)(tau_base + row0 + 8)*128 + d0;
            *(float2*)&outh[tA] = make_float2(y[t][0], y[t][1]);
            *(float2*)&outh[tB] = make_float2(y[t][2], y[t][3]);
        }
        __syncthreads();   // protect hs before next tile's prologue
    }
}

// ---------------------------------------------------------------------------
extern "C" void kernel_launch(void* const* d_in, const int* in_sizes, int n_in,
                              void* d_out, int out_size)
{
    const float* x_r  = (const float*)d_in[0];
    const float* x_i  = (const float*)d_in[1];
    const float* logA = (const float*)d_in[2];
    const float* Aph  = (const float*)d_in[3];
    const float* Bwr  = (const float*)d_in[4];
    const float* Bwi  = (const float*)d_in[5];
    const float* Cwr  = (const float*)d_in[6];
    const float* Cwi  = (const float*)d_in[7];
    const float* dtw  = (const float*)d_in[8];
    const float* dtb  = (const float*)d_in[9];
    float* out = (float*)d_out;

    const int smem1 = (72*136*2 + 1024) * 4;          // 82,432 B
    const int smem3 = (128*72*2 + 64*136) * 4;        // 108,544 B
    cudaFuncSetAttribute(k1_mma, cudaFuncAttributeMaxDynamicSharedMemorySize, smem1);
    cudaFuncSetAttribute(k3_mma, cudaFuncAttributeMaxDynamicSharedMemorySize, smem3);

    k1_mma<<<296, 256, smem1>>>(x_r, x_i, logA, Aph, Bwr, Bwi, dtw, dtb);
    k2b_combine<<<BG, 64>>>();
    k3_mma<<<296, 512, smem3>>>(Cwr, Cwi, out);
}